// round 4
// baseline (speedup 1.0000x reference)
#include <cuda_runtime.h>
#include <math.h>

#define NT 256
#define TILE 16
#define SEQ 5
#define ROWS (TILE*SEQ)
#define EMAX 150016
#define NMAX 50048

static __device__ float    g_eft[(size_t)EMAX * 512];
static __device__ float    g_a[EMAX * 8];
static __device__ float    g_aexp[EMAX * 8];
static __device__ unsigned g_mx[NMAX * 8];
static __device__ float    g_sm[NMAX * 8];

// smem layout in floats
#define O_TOK  0
#define O_X    (O_TOK + ROWS*64)
#define O_BUF  (O_X + ROWS*64)            // [80][192] / [16][256]
#define O_W    (O_BUF + ROWS*192)         // up to 17408
#define O_INST (O_W + 17408)
#define O_Q    (O_INST + TILE*64)
#define O_FV   (O_Q + TILE*64)
#define O_DEN  (O_FV + ROWS)
#define O_INT  (O_DEN + TILE)             // ints: idx[80], dst[16], lid[16]
#define SMEM_FLOATS (O_INT + 112)
#define SMEM_BYTES (SMEM_FLOATS*4)

__device__ __forceinline__ float d4(float4 a, float4 b){
    return a.x*b.x + a.y*b.y + a.z*b.z + a.w*b.w;
}
__device__ __forceinline__ float warpSum(float v){
#pragma unroll
    for (int o=16;o>0;o>>=1) v += __shfl_xor_sync(0xffffffffu, v, o);
    return v;
}
__device__ __forceinline__ float geluf(float x){
    return 0.5f*x*(1.0f+erff(x*0.70710678118654752f));
}
__device__ __forceinline__ unsigned fkey(float f){
    unsigned u = __float_as_uint(f);
    return (u & 0x80000000u) ? ~u : (u | 0x80000000u);
}
__device__ __forceinline__ float kdec(unsigned k){
    return (k & 0x80000000u) ? __uint_as_float(k & 0x7fffffffu) : __uint_as_float(~k);
}

// out[M][ldo] (+=|=) X[M][ldx] @ W[NC][ldw]^T + bias ; W staged in smem, K<=256
__device__ void sgemm(float* out,int ldo,const float* X,int ldx,
                      const float* W,int ldw,const float* bias,
                      int M,int NC,int K,bool acc,int tid){
    int ntc = NC >> 2, total = (M >> 2) * ntc;
    for (int t = tid; t < total; t += NT){
        int r0 = (t / ntc) << 2, c0 = (t % ntc) << 2;
        float a[4][4] = {{0.f}};
        for (int k = 0; k < K; k += 4){
            float4 xv[4], wv[4];
#pragma unroll
            for (int i=0;i<4;i++) xv[i] = *(const float4*)(X + (r0+i)*ldx + k);
#pragma unroll
            for (int j=0;j<4;j++) wv[j] = *(const float4*)(W + (c0+j)*ldw + k);
#pragma unroll
            for (int i=0;i<4;i++)
#pragma unroll
                for (int j=0;j<4;j++) a[i][j] += d4(xv[i], wv[j]);
        }
#pragma unroll
        for (int i=0;i<4;i++)
#pragma unroll
            for (int j=0;j<4;j++){
                float v = a[i][j] + __ldg(bias + c0 + j);
                float* p = out + (r0+i)*ldo + c0 + j;
                if (acc) *p += v; else *p = v;
            }
    }
}

__device__ void stage(float* dst,const float* src,int rows,int K,int ldw,int tid){
    int k4 = K >> 2;
    for (int i = tid; i < rows*k4; i += NT){
        int r = i / k4, c = i - r*k4;
        *(float4*)(dst + r*ldw + c*4) = __ldg((const float4*)(src + r*K + c*4));
    }
}

__device__ void ln_rows(const float* in,float* out,int nrows,
                        const float* g,const float* b,int tid){
    int warp = tid >> 5, lane = tid & 31;
    for (int r = warp; r < nrows; r += 8){
        float x0 = in[r*64+lane], x1 = in[r*64+lane+32];
        float s  = warpSum(x0+x1);
        float s2 = warpSum(x0*x0 + x1*x1);
        float m  = s*(1.f/64.f);
        float v  = fmaxf(s2*(1.f/64.f) - m*m, 0.f);
        float rs = rsqrtf(v + 1e-5f);
        out[r*64+lane]    = (x0-m)*rs*__ldg(g+lane)    + __ldg(b+lane);
        out[r*64+lane+32] = (x1-m)*rs*__ldg(g+lane+32) + __ldg(b+lane+32);
    }
}

__global__ void __launch_bounds__(NT,1)
k_mega(const float* __restrict__ feat,const float* __restrict__ pos,
       const float* __restrict__ siw,const float* __restrict__ sib,
       const float* __restrict__ sow,const float* __restrict__ sob,
       const float* __restrict__ ciw,const float* __restrict__ cib,
       const float* __restrict__ cow,const float* __restrict__ cob,
       const float* __restrict__ sl1g,const float* __restrict__ sl1b,
       const float* __restrict__ sl2g,const float* __restrict__ sl2b,
       const float* __restrict__ cl1g,const float* __restrict__ cl1b,
       const float* __restrict__ cl2g,const float* __restrict__ cl2b,
       const float* __restrict__ fw1,const float* __restrict__ fb1,
       const float* __restrict__ fw2,const float* __restrict__ fb2,
       const float* __restrict__ gw1,const float* __restrict__ gb1,
       const float* __restrict__ gw2,const float* __restrict__ gb2,
       const float* __restrict__ iw,const float* __restrict__ av,
       const int* __restrict__ eidx,const int* __restrict__ dst,int N,int E)
{
    extern __shared__ float sm[];
    float* s_tok = sm + O_TOK;  float* s_x = sm + O_X;
    float* s_buf = sm + O_BUF;  float* s_w = sm + O_W;
    float* s_inst= sm + O_INST; float* s_q = sm + O_Q;
    float* s_fv  = sm + O_FV;   float* s_den = sm + O_DEN;
    int* s_idx = (int*)(sm + O_INT);
    int* s_dst = s_idx + ROWS;  int* s_lid = s_dst + TILE;
    int tid = threadIdx.x, e0 = blockIdx.x * TILE;

    // S0: indices, validity, per-edge stats, gather tokens(+pos)
    if (tid < ROWS){
        int e = tid/SEQ, s = tid - e*SEQ, ge = e0 + e;
        int id = (ge < E) ? eidx[ge*SEQ + s] : N;
        s_idx[tid] = id; s_fv[tid] = (id < N) ? 1.f : 0.f;
    }
    __syncthreads();
    if (tid < TILE){
        float c = 0.f;
        for (int s=0;s<SEQ;s++) c += s_fv[tid*SEQ+s];
        s_den[tid] = fmaxf(c, 1.f);
        int lp = (c > 0.f) ? (int)c - 1 : 0;
        s_lid[tid] = s_idx[tid*SEQ + lp];
        int ge = e0 + tid;
        s_dst[tid] = (ge < E) ? dst[ge] : 0;
    }
    for (int i = tid; i < ROWS*64; i += NT){
        int r = i>>6, c = i&63, s = r%SEQ, id = s_idx[r];
        s_tok[i] = (id < N) ? __ldg(feat + (size_t)id*64 + c) + __ldg(pos + s*64 + c) : 0.f;
    }
    __syncthreads();

    // S1: LN1 + QKV
    ln_rows(s_tok, s_x, ROWS, sl1g, sl1b, tid);
    stage(s_w, siw, 192, 64, 68, tid);
    __syncthreads();
    sgemm(s_buf, 192, s_x, 64, s_w, 68, sib, ROWS, 192, 64, false, tid);
    __syncthreads();

    // S2: self attention per (edge, head)
    if (tid < TILE*8){
        int e = tid>>3, h = tid&7;
        const float* b = s_buf + e*SEQ*192;
#pragma unroll
        for (int qs=0; qs<SEQ; qs++){
            float sc[SEQ], mx = -1e30f;
#pragma unroll
            for (int ks=0; ks<SEQ; ks++){
                float s = 0.f;
#pragma unroll
                for (int d=0; d<8; d++) s += b[qs*192+h*8+d]*b[ks*192+64+h*8+d];
                s *= 0.35355339059327373f;
                if (s_fv[e*SEQ+ks] == 0.f) s = -1e9f;
                sc[ks] = s; mx = fmaxf(mx, s);
            }
            float sum = 0.f;
#pragma unroll
            for (int ks=0; ks<SEQ; ks++){ sc[ks] = expf(sc[ks]-mx); sum += sc[ks]; }
            float inv = 1.f/sum;
#pragma unroll
            for (int d=0; d<8; d++){
                float o = 0.f;
#pragma unroll
                for (int ks=0; ks<SEQ; ks++) o += sc[ks]*b[ks*192+128+h*8+d];
                s_x[(e*SEQ+qs)*64 + h*8 + d] = o*inv;
            }
        }
    }
    __syncthreads();
    stage(s_w, sow, 64, 64, 68, tid);
    __syncthreads();
    sgemm(s_tok, 64, s_x, 64, s_w, 68, sob, ROWS, 64, 64, true, tid);
    __syncthreads();

    // S3: masked mean pool
    for (int i = tid; i < TILE*64; i += NT){
        int e = i>>6, c = i&63; float s = 0.f;
#pragma unroll
        for (int ss=0; ss<SEQ; ss++) s += s_fv[e*SEQ+ss]*s_tok[(e*SEQ+ss)*64+c];
        s_inst[i] = s / s_den[e];
    }
    __syncthreads();

    // S4: FF (sa)
    ln_rows(s_inst, s_x, TILE, sl2g, sl2b, tid);
    stage(s_w, fw1, 256, 64, 68, tid);
    __syncthreads();
    sgemm(s_buf, 256, s_x, 64, s_w, 68, fb1, TILE, 256, 64, false, tid);
    __syncthreads();
    for (int i = tid; i < TILE*256; i += NT) s_buf[i] = geluf(s_buf[i]);
    stage(s_w, fw2, 64, 256, 260, tid);
    __syncthreads();
    sgemm(s_inst, 64, s_buf, 256, s_w, 260, fb2, TILE, 64, 256, true, tid);
    __syncthreads();

    // S5: cross attention
    for (int i = tid; i < TILE*64; i += NT){
        int e = i>>6, c = i&63, id = s_lid[e];
        s_x[i] = (id < N) ? __ldg(feat + (size_t)id*64 + c) : 0.f;
    }
    __syncthreads();
    ln_rows(s_x, s_x, TILE, cl1g, cl1b, tid);
    stage(s_w, ciw, 192, 64, 68, tid);
    __syncthreads();
    sgemm(s_q, 64, s_x, 64, s_w, 68, cib, TILE, 64, 64, false, tid);
    sgemm(s_buf+64, 192, s_tok, 64, s_w+64*68, 68, cib+64, ROWS, 128, 64, false, tid);
    __syncthreads();
    if (tid < TILE*8){
        int e = tid>>3, h = tid&7;
        float qv[8], sc[SEQ], mx = -1e30f;
#pragma unroll
        for (int d=0; d<8; d++) qv[d] = s_q[e*64+h*8+d];
#pragma unroll
        for (int ks=0; ks<SEQ; ks++){
            float s = 0.f;
#pragma unroll
            for (int d=0; d<8; d++) s += qv[d]*s_buf[(e*SEQ+ks)*192+64+h*8+d];
            s *= 0.35355339059327373f;
            if (s_fv[e*SEQ+ks] == 0.f) s = -1e9f;
            sc[ks] = s; mx = fmaxf(mx, s);
        }
        float sum = 0.f;
#pragma unroll
        for (int ks=0; ks<SEQ; ks++){ sc[ks] = expf(sc[ks]-mx); sum += sc[ks]; }
        float inv = 1.f/sum;
#pragma unroll
        for (int d=0; d<8; d++){
            float o = 0.f;
#pragma unroll
            for (int ks=0; ks<SEQ; ks++) o += sc[ks]*s_buf[(e*SEQ+ks)*192+128+h*8+d];
            s_x[e*64+h*8+d] = o*inv;
        }
    }
    __syncthreads();
    stage(s_w, cow, 64, 64, 68, tid);
    __syncthreads();
    sgemm(s_inst, 64, s_x, 64, s_w, 68, cob, TILE, 64, 64, true, tid);
    __syncthreads();

    // S6: FF (ca)
    ln_rows(s_inst, s_x, TILE, cl2g, cl2b, tid);
    stage(s_w, gw1, 256, 64, 68, tid);
    __syncthreads();
    sgemm(s_buf, 256, s_x, 64, s_w, 68, gb1, TILE, 256, 64, false, tid);
    __syncthreads();
    for (int i = tid; i < TILE*256; i += NT) s_buf[i] = geluf(s_buf[i]);
    stage(s_w, gw2, 64, 256, 260, tid);
    __syncthreads();
    sgemm(s_inst, 64, s_buf, 256, s_w, 260, gb2, TILE, 64, 256, true, tid);
    __syncthreads();

    // S7: eft = inst @ inst_w^T, 2 chunks of 256 cols; leaky score + seg max
    for (int ch = 0; ch < 2; ch++){
        stage(s_w, iw + ch*256*64, 256, 64, 68, tid);
        __syncthreads();
        sgemm(s_buf, 256, s_inst, 64, s_w, 68, (const float*)g_sm /*dummy*/, TILE, 256, 64, false, tid);
        __syncthreads();
        // fix: bias-free gemm: subtract the dummy bias we just added
        // (instead, recompute cleanly below) -- handled by using zero bias:
        __syncthreads();
        for (int i = tid; i < TILE*256; i += NT){
            int r = i>>8, c = i&255, ge = e0 + r;
            if (ge < E) g_eft[(size_t)ge*512 + ch*256 + c] = s_buf[i];
        }
        if (tid < TILE*4){
            int e = tid>>2, h4 = tid&3, h = ch*4+h4, ge = e0 + e;
            float v = 0.f;
            for (int d=0; d<64; d++) v += s_buf[e*256 + h4*64 + d]*__ldg(av + h*64 + d);
            v = (v > 0.f) ? v : 0.01f*v;
            if (ge < E){
                g_a[ge*8+h] = v;
                atomicMax(&g_mx[(size_t)s_dst[e]*8 + h], fkey(v));
            }
        }
        __syncthreads();
    }
}

__global__ void k_zero_eftbias(){ }  // placeholder (unused)

__global__ void k_init(float* out, long long total, int n8){
    long long i = (long long)blockIdx.x*NT + threadIdx.x;
    if (i < total) out[i] = 0.f;
    if (i < n8){ g_mx[i] = 0u; g_sm[i] = 0.f; }
}

__global__ void k_exp(const int* __restrict__ dst, int E){
    int i = blockIdx.x*NT + threadIdx.x;
    if (i >= E*8) return;
    int e = i>>3, h = i&7, d = dst[e];
    float ae = expf(g_a[i] - kdec(g_mx[(size_t)d*8+h]));
    g_aexp[i] = ae;
    atomicAdd(&g_sm[(size_t)d*8+h], ae);
}

__global__ void k_scatter(const int* __restrict__ dst, float* __restrict__ out, int E){
    int t = blockIdx.x*NT + threadIdx.x;
    int e = t >> 7;                 // 128 threads per edge
    if (e >= E) return;
    int j = (t & 127) * 4, h = j >> 6, d = dst[e];
    float w = g_aexp[e*8+h] / g_sm[(size_t)d*8+h];
    float4 v = *(const float4*)(g_eft + (size_t)e*512 + j);
    float* p = out + (size_t)d*512 + j;
    atomicAdd(p+0, v.x*w); atomicAdd(p+1, v.y*w);
    atomicAdd(p+2, v.z*w); atomicAdd(p+3, v.w*w);
}

extern "C" void kernel_launch(void* const* d_in, const int* in_sizes, int n_in,
                              void* d_out, int out_size)
{
    const float* feat=(const float*)d_in[0];  const float* pos=(const float*)d_in[1];
    const float* siw=(const float*)d_in[2];   const float* sib=(const float*)d_in[3];
    const float* sow=(const float*)d_in[4];   const float* sob=(const float*)d_in[5];
    const float* ciw=(const float*)d_in[6];   const float* cib=(const float*)d_in[7];
    const float* cow=(const float*)d_in[8];   const float* cob=(const float*)d_in[9];
    const float* sl1g=(const float*)d_in[10]; const float* sl1b=(const float*)d_in[11];
    const float* sl2g=(const float*)d_in[12]; const float* sl2b=(const float*)d_in[13];
    const float* cl1g=(const float*)d_in[14]; const float* cl1b=(const float*)d_in[15];
    const float* cl2g=(const float*)d_in[16]; const float* cl2b=(const float*)d_in[17];
    const float* fw1=(const float*)d_in[18];  const float* fb1=(const float*)d_in[19];
    const float* fw2=(const float*)d_in[20];  const float* fb2=(const float*)d_in[21];
    const float* gw1=(const float*)d_in[22];  const float* gb1=(const float*)d_in[23];
    const float* gw2=(const float*)d_in[24];  const float* gb2=(const float*)d_in[25];
    const float* iw=(const float*)d_in[26];   const float* av=(const float*)d_in[27];
    const int* eidx=(const int*)d_in[28];     const int* dst=(const int*)d_in[29];

    int N = in_sizes[0] / 64;
    int E = in_sizes[29];
    float* out = (float*)d_out;
    long long total = (long long)N * 512;

    static int attr_done = 0;
    if (!attr_done){
        cudaFuncSetAttribute(k_mega, cudaFuncAttributeMaxDynamicSharedMemorySize, SMEM_BYTES);
        attr_done = 1;
    }

    k_init<<<(unsigned)((total + NT-1)/NT), NT>>>(out, total, N*8);
    int tiles = (E + TILE - 1) / TILE;
    k_mega<<<tiles, NT, SMEM_BYTES>>>(feat,pos,siw,sib,sow,sob,ciw,cib,cow,cob,
        sl1g,sl1b,sl2g,sl2b,cl1g,cl1b,cl2g,cl2b,
        fw1,fb1,fw2,fb2,gw1,gb1,gw2,gb2,iw,av,eidx,dst,N,E);
    k_exp<<<(E*8 + NT-1)/NT, NT>>>(dst, E);
    k_scatter<<<(E*128 + NT-1)/NT, NT>>>(dst, out, E);
}

// round 6
// speedup vs baseline: 1.4399x; 1.4399x over previous
#include <cuda_runtime.h>
#include <math.h>

#define NT 256
#define TILE 16
#define SEQ 5
#define ROWS (TILE*SEQ)
#define EMAX 150016
#define NMAX 50048

static __device__ float    g_eft[(size_t)EMAX * 512];
static __device__ float    g_a[EMAX * 8];
static __device__ float    g_aexp[EMAX * 8];
static __device__ unsigned g_mx[NMAX * 8];
static __device__ float    g_sm[NMAX * 8];

// smem layout (floats)
#define O_TOK  0
#define O_X    (O_TOK + ROWS*64)
#define O_BUF  (O_X + ROWS*64)            // [80][192] / [16][256]
#define O_W    (O_BUF + ROWS*192)         // <= 17408 floats staged weights
#define O_INST (O_W + 17408)
#define O_Q    (O_INST + TILE*64)
#define O_FV   (O_Q + TILE*64)
#define O_DEN  (O_FV + ROWS)
#define O_INT  (O_DEN + TILE)
#define SMEM_FLOATS (O_INT + 112)
#define SMEM_BYTES (SMEM_FLOATS*4)

__device__ __forceinline__ float d4(float4 a, float4 b){
    return a.x*b.x + a.y*b.y + a.z*b.z + a.w*b.w;
}
__device__ __forceinline__ float warpSum(float v){
#pragma unroll
    for (int o=16;o>0;o>>=1) v += __shfl_xor_sync(0xffffffffu, v, o);
    return v;
}
__device__ __forceinline__ float geluf(float x){
    return 0.5f*x*(1.0f+erff(x*0.70710678118654752f));
}
__device__ __forceinline__ unsigned fkey(float f){
    unsigned u = __float_as_uint(f);
    return (u & 0x80000000u) ? ~u : (u | 0x80000000u);
}
__device__ __forceinline__ float kdec(unsigned k){
    return (k & 0x80000000u) ? __uint_as_float(k & 0x7fffffffu) : __uint_as_float(~k);
}

// M=80 GEMM: out[80][ldo] op= X[80][ldx(bcast rows)] @ W[NC][ldw]^T + bias.
// Thread handles 2 columns (col, col+NC/2) x 16 rows. X loads warp-broadcast.
__device__ void gemm80(float* out,int ldo,const float* X,int ldx,
                       const float* W,int ldw,const float* bias,
                       int NC,bool acc,int tid){
    int ncc = NC >> 1;
    int total = ncc * 5;
    for (int t = tid; t < total; t += NT){
        int col = t % ncc;
        int r0  = (t / ncc) * 16;
        const float* W0 = W + col*ldw;
        const float* W1 = W + (col+ncc)*ldw;
        float a0[16], a1[16];
#pragma unroll
        for (int i=0;i<16;i++){ a0[i]=0.f; a1[i]=0.f; }
        for (int k=0;k<64;k+=4){
            float4 w0 = *(const float4*)(W0 + k);
            float4 w1 = *(const float4*)(W1 + k);
#pragma unroll
            for (int i=0;i<16;i++){
                float4 xv = *(const float4*)(X + (r0+i)*ldx + k);
                a0[i] += d4(xv,w0);
                a1[i] += d4(xv,w1);
            }
        }
        float b0 = __ldg(bias+col), b1 = __ldg(bias+col+ncc);
#pragma unroll
        for (int i=0;i<16;i++){
            float* p0 = out + (r0+i)*ldo + col;
            float* p1 = out + (r0+i)*ldo + col + ncc;
            if (acc){ *p0 += a0[i]+b0; *p1 += a1[i]+b1; }
            else    { *p0  = a0[i]+b0; *p1  = a1[i]+b1; }
        }
    }
}

// M=16 GEMM with split-K: KS = NT/NC slices. s_part needs KS*16*NC floats (<=4096).
__device__ void gemm16(float* out,int ldo,const float* X,int ldx,
                       const float* W,int ldw,const float* bias,
                       int NC,int K,bool acc,int tid,float* s_part){
    int KS = NT / NC; if (KS < 1) KS = 1;
    int kl = K / KS;
    int nt = NC * KS;
    if (KS == 1){
        if (tid < NC){
            int col = tid;
            const float* Wc = W + col*ldw;
            float a[16];
#pragma unroll
            for (int i=0;i<16;i++) a[i]=0.f;
            for (int k=0;k<K;k+=4){
                float4 wv = *(const float4*)(Wc + k);
#pragma unroll
                for (int i=0;i<16;i++){
                    float4 xv = *(const float4*)(X + i*ldx + k);
                    a[i] += d4(xv,wv);
                }
            }
            float bv = bias ? __ldg(bias+col) : 0.f;
#pragma unroll
            for (int i=0;i<16;i++){
                float* p = out + i*ldo + col;
                if (acc) *p += a[i]+bv; else *p = a[i]+bv;
            }
        }
        return;
    }
    if (tid < nt){
        int col = tid % NC, ks = tid / NC;
        const float* Wc = W + col*ldw + ks*kl;
        const float* Xc = X + ks*kl;
        float a[16];
#pragma unroll
        for (int i=0;i<16;i++) a[i]=0.f;
        for (int k=0;k<kl;k+=4){
            float4 wv = *(const float4*)(Wc + k);
#pragma unroll
            for (int i=0;i<16;i++){
                float4 xv = *(const float4*)(Xc + i*ldx + k);
                a[i] += d4(xv,wv);
            }
        }
        float* pp = s_part + ks*NC*16 + col;
#pragma unroll
        for (int i=0;i<16;i++) pp[i*NC] = a[i];
    }
    __syncthreads();
    for (int i = tid; i < 16*NC; i += NT){
        int col = i % NC;
        float s = 0.f;
        for (int ks=0; ks<KS; ks++) s += s_part[ks*NC*16 + i];
        float v = s + (bias ? __ldg(bias+col) : 0.f);
        float* p = out + (i/NC)*ldo + col;
        if (acc) *p += v; else *p = v;
    }
}

__device__ void stage(float* dst,const float* src,int rows,int K,int ldw,int tid){
    int k4 = K >> 2;
    for (int i = tid; i < rows*k4; i += NT){
        int r = i / k4, c = i - r*k4;
        *(float4*)(dst + r*ldw + c*4) = __ldg((const float4*)(src + r*K + c*4));
    }
}

__device__ void ln_rows(const float* in,float* out,int nrows,
                        const float* g,const float* b,int tid){
    int warp = tid >> 5, lane = tid & 31;
    for (int r = warp; r < nrows; r += 8){
        float x0 = in[r*64+lane], x1 = in[r*64+lane+32];
        float s  = warpSum(x0+x1);
        float s2 = warpSum(x0*x0 + x1*x1);
        float m  = s*(1.f/64.f);
        float v  = fmaxf(s2*(1.f/64.f) - m*m, 0.f);
        float rs = rsqrtf(v + 1e-5f);
        out[r*64+lane]    = (x0-m)*rs*__ldg(g+lane)    + __ldg(b+lane);
        out[r*64+lane+32] = (x1-m)*rs*__ldg(g+lane+32) + __ldg(b+lane+32);
    }
}

__global__ void __launch_bounds__(NT,1)
k_mega(const float* __restrict__ feat,const float* __restrict__ pos,
       const float* __restrict__ siw,const float* __restrict__ sib,
       const float* __restrict__ sow,const float* __restrict__ sob,
       const float* __restrict__ ciw,const float* __restrict__ cib,
       const float* __restrict__ cow,const float* __restrict__ cob,
       const float* __restrict__ sl1g,const float* __restrict__ sl1b,
       const float* __restrict__ sl2g,const float* __restrict__ sl2b,
       const float* __restrict__ cl1g,const float* __restrict__ cl1b,
       const float* __restrict__ cl2g,const float* __restrict__ cl2b,
       const float* __restrict__ fw1,const float* __restrict__ fb1,
       const float* __restrict__ fw2,const float* __restrict__ fb2,
       const float* __restrict__ gw1,const float* __restrict__ gb1,
       const float* __restrict__ gw2,const float* __restrict__ gb2,
       const float* __restrict__ iw,const float* __restrict__ av,
       const int* __restrict__ eidx,const int* __restrict__ dst,int N,int E)
{
    extern __shared__ float sm[];
    float* s_tok = sm + O_TOK;  float* s_x = sm + O_X;
    float* s_buf = sm + O_BUF;  float* s_w = sm + O_W;
    float* s_inst= sm + O_INST; float* s_q = sm + O_Q;
    float* s_fv  = sm + O_FV;   float* s_den = sm + O_DEN;
    int* s_idx = (int*)(sm + O_INT);
    int* s_dst = s_idx + ROWS;  int* s_lid = s_dst + TILE;
    int tid = threadIdx.x, e0 = blockIdx.x * TILE;

    // S0: indices, validity, stats, gather tokens(+pos)
    if (tid < ROWS){
        int e = tid/SEQ, s = tid - e*SEQ, ge = e0 + e;
        int id = (ge < E) ? eidx[ge*SEQ + s] : N;
        s_idx[tid] = id; s_fv[tid] = (id < N) ? 1.f : 0.f;
    }
    __syncthreads();
    if (tid < TILE){
        float c = 0.f;
        for (int s=0;s<SEQ;s++) c += s_fv[tid*SEQ+s];
        s_den[tid] = fmaxf(c, 1.f);
        int lp = (c > 0.f) ? (int)c - 1 : 0;
        s_lid[tid] = s_idx[tid*SEQ + lp];
        int ge = e0 + tid;
        s_dst[tid] = (ge < E) ? dst[ge] : 0;
    }
    for (int i = tid; i < ROWS*64; i += NT){
        int r = i>>6, c = i&63, s = r%SEQ, id = s_idx[r];
        s_tok[i] = (id < N) ? __ldg(feat + (size_t)id*64 + c) + __ldg(pos + s*64 + c) : 0.f;
    }
    __syncthreads();

    // S1: LN1 + QKV (M=80, NC=192)
    ln_rows(s_tok, s_x, ROWS, sl1g, sl1b, tid);
    stage(s_w, siw, 192, 64, 68, tid);
    __syncthreads();
    gemm80(s_buf, 192, s_x, 64, s_w, 68, sib, 192, false, tid);
    __syncthreads();

    // S2: self attention per (edge, head)
    if (tid < TILE*8){
        int e = tid>>3, h = tid&7;
        const float* b = s_buf + e*SEQ*192;
#pragma unroll
        for (int qs=0; qs<SEQ; qs++){
            float sc[SEQ], mx = -1e30f;
#pragma unroll
            for (int ks=0; ks<SEQ; ks++){
                float s = 0.f;
#pragma unroll
                for (int d=0; d<8; d++) s += b[qs*192+h*8+d]*b[ks*192+64+h*8+d];
                s *= 0.35355339059327373f;
                if (s_fv[e*SEQ+ks] == 0.f) s = -1e9f;
                sc[ks] = s; mx = fmaxf(mx, s);
            }
            float sum = 0.f;
#pragma unroll
            for (int ks=0; ks<SEQ; ks++){ sc[ks] = expf(sc[ks]-mx); sum += sc[ks]; }
            float inv = 1.f/sum;
#pragma unroll
            for (int d=0; d<8; d++){
                float o = 0.f;
#pragma unroll
                for (int ks=0; ks<SEQ; ks++) o += sc[ks]*b[ks*192+128+h*8+d];
                s_x[(e*SEQ+qs)*64 + h*8 + d] = o*inv;
            }
        }
    }
    stage(s_w, sow, 64, 64, 68, tid);
    __syncthreads();
    gemm80(s_tok, 64, s_x, 64, s_w, 68, sob, 64, true, tid);
    __syncthreads();

    // S3: masked mean pool
    for (int i = tid; i < TILE*64; i += NT){
        int e = i>>6, c = i&63; float s = 0.f;
#pragma unroll
        for (int ss=0; ss<SEQ; ss++) s += s_fv[e*SEQ+ss]*s_tok[(e*SEQ+ss)*64+c];
        s_inst[i] = s / s_den[e];
    }
    __syncthreads();

    // S4: FF (sa)
    ln_rows(s_inst, s_x, TILE, sl2g, sl2b, tid);
    stage(s_w, fw1, 256, 64, 68, tid);
    __syncthreads();
    gemm16(s_buf, 256, s_x, 64, s_w, 68, fb1, 256, 64, false, tid, s_x+1024);
    __syncthreads();
    for (int i = tid; i < TILE*256; i += NT) s_buf[i] = geluf(s_buf[i]);
    stage(s_w, fw2, 64, 256, 260, tid);
    __syncthreads();
    gemm16(s_inst, 64, s_buf, 256, s_w, 260, fb2, 64, 256, true, tid, s_x);
    __syncthreads();

    // S5: cross attention
    for (int i = tid; i < TILE*64; i += NT){
        int e = i>>6, c = i&63, id = s_lid[e];
        s_x[i] = (id < N) ? __ldg(feat + (size_t)id*64 + c) : 0.f;
    }
    __syncthreads();
    ln_rows(s_x, s_x, TILE, cl1g, cl1b, tid);
    stage(s_w, ciw, 192, 64, 68, tid);
    __syncthreads();
    gemm16(s_q, 64, s_x, 64, s_w, 68, cib, 64, 64, false, tid, s_x+1024);
    __syncthreads();
    gemm80(s_buf+64, 192, s_tok, 64, s_w+64*68, 68, cib+64, 128, false, tid);
    __syncthreads();
    if (tid < TILE*8){
        int e = tid>>3, h = tid&7;
        float qv[8], sc[SEQ], mx = -1e30f;
#pragma unroll
        for (int d=0; d<8; d++) qv[d] = s_q[e*64+h*8+d];
#pragma unroll
        for (int ks=0; ks<SEQ; ks++){
            float s = 0.f;
#pragma unroll
            for (int d=0; d<8; d++) s += qv[d]*s_buf[(e*SEQ+ks)*192+64+h*8+d];
            s *= 0.35355339059327373f;
            if (s_fv[e*SEQ+ks] == 0.f) s = -1e9f;
            sc[ks] = s; mx = fmaxf(mx, s);
        }
        float sum = 0.f;
#pragma unroll
        for (int ks=0; ks<SEQ; ks++){ sc[ks] = expf(sc[ks]-mx); sum += sc[ks]; }
        float inv = 1.f/sum;
#pragma unroll
        for (int d=0; d<8; d++){
            float o = 0.f;
#pragma unroll
            for (int ks=0; ks<SEQ; ks++) o += sc[ks]*s_buf[(e*SEQ+ks)*192+128+h*8+d];
            s_x[e*64+h*8+d] = o*inv;
        }
    }
    stage(s_w, cow, 64, 64, 68, tid);
    __syncthreads();
    gemm16(s_inst, 64, s_x, 64, s_w, 68, cob, 64, 64, true, tid, s_x+1024);
    __syncthreads();

    // S6: FF (ca)
    ln_rows(s_inst, s_x, TILE, cl2g, cl2b, tid);
    stage(s_w, gw1, 256, 64, 68, tid);
    __syncthreads();
    gemm16(s_buf, 256, s_x, 64, s_w, 68, gb1, 256, 64, false, tid, s_x+1024);
    __syncthreads();
    for (int i = tid; i < TILE*256; i += NT) s_buf[i] = geluf(s_buf[i]);
    stage(s_w, gw2, 64, 256, 260, tid);
    __syncthreads();
    gemm16(s_inst, 64, s_buf, 256, s_w, 260, gb2, 64, 256, true, tid, s_x);
    __syncthreads();

    // S7: eft = inst @ inst_w^T (2 chunks of 256 cols) + score + seg max
    for (int ch = 0; ch < 2; ch++){
        stage(s_w, iw + ch*256*64, 256, 64, 68, tid);
        __syncthreads();
        gemm16(s_buf, 256, s_inst, 64, s_w, 68, (const float*)0, 256, 64, false, tid, s_x);
        __syncthreads();
        for (int i = tid; i < TILE*256; i += NT){
            int r = i>>8, c = i&255, ge = e0 + r;
            if (ge < E) g_eft[(size_t)ge*512 + ch*256 + c] = s_buf[i];
        }
        if (tid < TILE*4){
            int e = tid>>2, h4 = tid&3, h = ch*4+h4, ge = e0 + e;
            float v = 0.f;
            for (int d=0; d<64; d++) v += s_buf[e*256 + h4*64 + d]*__ldg(av + h*64 + d);
            v = (v > 0.f) ? v : 0.01f*v;
            if (ge < E){
                g_a[ge*8+h] = v;
                atomicMax(&g_mx[(size_t)s_dst[e]*8 + h], fkey(v));
            }
        }
        __syncthreads();
    }
}

__global__ void k_init(float* out, long long total, int n8){
    long long i = (long long)blockIdx.x*NT + threadIdx.x;
    if (i < total) out[i] = 0.f;
    if (i < n8){ g_mx[i] = 0u; g_sm[i] = 0.f; }
}

__global__ void k_exp(const int* __restrict__ dst, int E){
    int i = blockIdx.x*NT + threadIdx.x;
    if (i >= E*8) return;
    int e = i>>3, h = i&7, d = dst[e];
    float ae = expf(g_a[i] - kdec(g_mx[(size_t)d*8+h]));
    g_aexp[i] = ae;
    atomicAdd(&g_sm[(size_t)d*8+h], ae);
}

__global__ void k_scatter(const int* __restrict__ dst, float* __restrict__ out, int E){
    int t = blockIdx.x*NT + threadIdx.x;
    int e = t >> 7;
    if (e >= E) return;
    int j = (t & 127) * 4, h = j >> 6, d = dst[e];
    float w = g_aexp[e*8+h] / g_sm[(size_t)d*8+h];
    float4 v = *(const float4*)(g_eft + (size_t)e*512 + j);
    float* p = out + (size_t)d*512 + j;
    atomicAdd(p+0, v.x*w); atomicAdd(p+1, v.y*w);
    atomicAdd(p+2, v.z*w); atomicAdd(p+3, v.w*w);
}

extern "C" void kernel_launch(void* const* d_in, const int* in_sizes, int n_in,
                              void* d_out, int out_size)
{
    const float* feat=(const float*)d_in[0];  const float* pos=(const float*)d_in[1];
    const float* siw=(const float*)d_in[2];   const float* sib=(const float*)d_in[3];
    const float* sow=(const float*)d_in[4];   const float* sob=(const float*)d_in[5];
    const float* ciw=(const float*)d_in[6];   const float* cib=(const float*)d_in[7];
    const float* cow=(const float*)d_in[8];   const float* cob=(const float*)d_in[9];
    const float* sl1g=(const float*)d_in[10]; const float* sl1b=(const float*)d_in[11];
    const float* sl2g=(const float*)d_in[12]; const float* sl2b=(const float*)d_in[13];
    const float* cl1g=(const float*)d_in[14]; const float* cl1b=(const float*)d_in[15];
    const float* cl2g=(const float*)d_in[16]; const float* cl2b=(const float*)d_in[17];
    const float* fw1=(const float*)d_in[18];  const float* fb1=(const float*)d_in[19];
    const float* fw2=(const float*)d_in[20];  const float* fb2=(const float*)d_in[21];
    const float* gw1=(const float*)d_in[22];  const float* gb1=(const float*)d_in[23];
    const float* gw2=(const float*)d_in[24];  const float* gb2=(const float*)d_in[25];
    const float* iw=(const float*)d_in[26];   const float* av=(const float*)d_in[27];
    const int* eidx=(const int*)d_in[28];     const int* dst=(const int*)d_in[29];

    int N = in_sizes[0] / 64;
    int E = in_sizes[29];
    float* out = (float*)d_out;
    long long total = (long long)N * 512;

    static int attr_done = 0;
    if (!attr_done){
        cudaFuncSetAttribute(k_mega, cudaFuncAttributeMaxDynamicSharedMemorySize, SMEM_BYTES);
        attr_done = 1;
    }

    k_init<<<(unsigned)((total + NT-1)/NT), NT>>>(out, total, N*8);
    int tiles = (E + TILE - 1) / TILE;
    k_mega<<<tiles, NT, SMEM_BYTES>>>(feat,pos,siw,sib,sow,sob,ciw,cib,cow,cob,
        sl1g,sl1b,sl2g,sl2b,cl1g,cl1b,cl2g,cl2b,
        fw1,fb1,fw2,fb2,gw1,gb1,gw2,gb2,iw,av,eidx,dst,N,E);
    k_exp<<<(E*8 + NT-1)/NT, NT>>>(dst, E);
    k_scatter<<<(E*128 + NT-1)/NT, NT>>>(dst, out, E);
}

// round 7
// speedup vs baseline: 1.6584x; 1.1518x over previous
#include <cuda_runtime.h>
#include <math.h>

#define NT 256
#define TILE 16
#define SEQ 5
#define ROWS (TILE*SEQ)
#define EMAX 150016
#define NMAX 50048

typedef unsigned long long ull;

static __device__ float    g_eft[(size_t)EMAX * 512];
static __device__ float    g_a[EMAX * 8];
static __device__ float    g_aexp[EMAX * 8];
static __device__ unsigned g_mx[NMAX * 8];
static __device__ float    g_sm[NMAX * 8];

// smem layout (floats)
#define O_TOK  0
#define O_X    (O_TOK + ROWS*64)
#define O_BUF  (O_X + ROWS*64)            // [80][192] / [16][256]
#define O_W    (O_BUF + ROWS*192)         // <= 17408 floats staged weights
#define O_INST (O_W + 17408)
#define O_Q    (O_INST + TILE*64)
#define O_FV   (O_Q + TILE*64)
#define O_DEN  (O_FV + ROWS)
#define O_INT  (O_DEN + TILE)
#define SMEM_FLOATS (O_INT + 112)
#define SMEM_BYTES (SMEM_FLOATS*4)

__device__ __forceinline__ void fma2(ull& c, ull a, ull b){
    asm("fma.rn.f32x2 %0, %1, %2, %0;" : "+l"(c) : "l"(a), "l"(b));
}
__device__ __forceinline__ float hsum2(ull c){
    float lo, hi;
    asm("mov.b64 {%0,%1}, %2;" : "=f"(lo), "=f"(hi) : "l"(c));
    return lo + hi;
}
__device__ __forceinline__ void unpack2(ull c, float& lo, float& hi){
    asm("mov.b64 {%0,%1}, %2;" : "=f"(lo), "=f"(hi) : "l"(c));
}
__device__ __forceinline__ ull bcast2(float s){
    ull r; asm("mov.b64 %0, {%1,%1};" : "=l"(r) : "f"(s)); return r;
}
__device__ __forceinline__ float warpSum(float v){
#pragma unroll
    for (int o=16;o>0;o>>=1) v += __shfl_xor_sync(0xffffffffu, v, o);
    return v;
}
__device__ __forceinline__ float geluf(float x){
    return 0.5f*x*(1.0f+erff(x*0.70710678118654752f));
}
__device__ __forceinline__ unsigned fkey(float f){
    unsigned u = __float_as_uint(f);
    return (u & 0x80000000u) ? ~u : (u | 0x80000000u);
}
__device__ __forceinline__ float kdec(unsigned k){
    return (k & 0x80000000u) ? __uint_as_float(k & 0x7fffffffu) : __uint_as_float(~k);
}

// M=80 GEMM: out[80][ldo] op= X[80][ldx]@W[NC][ldw]^T + bias. K=64.
// Task = 2 cols x 10 rows; tasks = (NC/2)*8 (exact multiples of NT for NC=64/128/192).
// X loads warp-broadcast; W rows 272B apart -> conflict-free. f32x2 packed FMA.
__device__ void gemm80(float* out,int ldo,const float* X,int ldx,
                       const float* W,int ldw,const float* bias,
                       int NC,bool acc,int tid){
    int ncc = NC >> 1;
    int total = ncc * 8;
    for (int t = tid; t < total; t += NT){
        int col = t % ncc;
        int r0  = (t / ncc) * 10;
        const float* W0 = W + col*ldw;
        const float* W1 = W + (col+ncc)*ldw;
        ull a0[10], a1[10];
#pragma unroll
        for (int i=0;i<10;i++){ a0[i]=0ull; a1[i]=0ull; }
        for (int k=0;k<64;k+=4){
            ulonglong2 w0 = *(const ulonglong2*)(W0 + k);
            ulonglong2 w1 = *(const ulonglong2*)(W1 + k);
#pragma unroll
            for (int i=0;i<10;i++){
                ulonglong2 xv = *(const ulonglong2*)(X + (r0+i)*ldx + k);
                fma2(a0[i], xv.x, w0.x); fma2(a0[i], xv.y, w0.y);
                fma2(a1[i], xv.x, w1.x); fma2(a1[i], xv.y, w1.y);
            }
        }
        float b0 = __ldg(bias+col), b1 = __ldg(bias+col+ncc);
#pragma unroll
        for (int i=0;i<10;i++){
            float v0 = hsum2(a0[i]) + b0;
            float v1 = hsum2(a1[i]) + b1;
            float* p0 = out + (r0+i)*ldo + col;
            float* p1 = out + (r0+i)*ldo + col + ncc;
            if (acc){ *p0 += v0; *p1 += v1; }
            else    { *p0  = v0; *p1  = v1; }
        }
    }
}

// M=16 GEMM, split-K when NC<NT. s_part needs (NT/NC)*16*NC = 4096 floats max.
__device__ void gemm16(float* out,int ldo,const float* X,int ldx,
                       const float* W,int ldw,const float* bias,
                       int NC,int K,bool acc,int tid,float* s_part){
    int KS = NT / NC; if (KS < 1) KS = 1;
    int kl = K / KS;
    if (KS == 1){
        if (tid < NC){
            const float* Wc = W + tid*ldw;
            ull a[16];
#pragma unroll
            for (int i=0;i<16;i++) a[i]=0ull;
            for (int k=0;k<K;k+=4){
                ulonglong2 wv = *(const ulonglong2*)(Wc + k);
#pragma unroll
                for (int i=0;i<16;i++){
                    ulonglong2 xv = *(const ulonglong2*)(X + i*ldx + k);
                    fma2(a[i], xv.x, wv.x); fma2(a[i], xv.y, wv.y);
                }
            }
            float bv = bias ? __ldg(bias+tid) : 0.f;
#pragma unroll
            for (int i=0;i<16;i++){
                float v = hsum2(a[i]) + bv;
                float* p = out + i*ldo + tid;
                if (acc) *p += v; else *p = v;
            }
        }
        return;
    }
    {
        int col = tid % NC, ks = tid / NC;
        const float* Wc = W + col*ldw + ks*kl;
        const float* Xc = X + ks*kl;
        ull a[16];
#pragma unroll
        for (int i=0;i<16;i++) a[i]=0ull;
        for (int k=0;k<kl;k+=4){
            ulonglong2 wv = *(const ulonglong2*)(Wc + k);
#pragma unroll
            for (int i=0;i<16;i++){
                ulonglong2 xv = *(const ulonglong2*)(Xc + i*ldx + k);
                fma2(a[i], xv.x, wv.x); fma2(a[i], xv.y, wv.y);
            }
        }
        float* pp = s_part + ks*NC*16 + col;
#pragma unroll
        for (int i=0;i<16;i++) pp[i*NC] = hsum2(a[i]);
    }
    __syncthreads();
    for (int i = tid; i < 16*NC; i += NT){
        int col = i % NC;
        float s = 0.f;
        for (int ks=0; ks<KS; ks++) s += s_part[ks*NC*16 + i];
        float v = s + (bias ? __ldg(bias+col) : 0.f);
        float* p = out + (i/NC)*ldo + col;
        if (acc) *p += v; else *p = v;
    }
}

__device__ void stage(float* dst,const float* src,int rows,int K,int ldw,int tid){
    int k4 = K >> 2;
    for (int i = tid; i < rows*k4; i += NT){
        int r = i / k4, c = i - r*k4;
        *(float4*)(dst + r*ldw + c*4) = __ldg((const float4*)(src + r*K + c*4));
    }
}

__device__ void ln_rows(const float* in,float* out,int nrows,
                        const float* g,const float* b,int tid){
    int warp = tid >> 5, lane = tid & 31;
    for (int r = warp; r < nrows; r += 8){
        float x0 = in[r*64+lane], x1 = in[r*64+lane+32];
        float s  = warpSum(x0+x1);
        float s2 = warpSum(x0*x0 + x1*x1);
        float m  = s*(1.f/64.f);
        float v  = fmaxf(s2*(1.f/64.f) - m*m, 0.f);
        float rs = rsqrtf(v + 1e-5f);
        out[r*64+lane]    = (x0-m)*rs*__ldg(g+lane)    + __ldg(b+lane);
        out[r*64+lane+32] = (x1-m)*rs*__ldg(g+lane+32) + __ldg(b+lane+32);
    }
}

__global__ void __launch_bounds__(NT,1)
k_mega(const float* __restrict__ feat,const float* __restrict__ pos,
       const float* __restrict__ siw,const float* __restrict__ sib,
       const float* __restrict__ sow,const float* __restrict__ sob,
       const float* __restrict__ ciw,const float* __restrict__ cib,
       const float* __restrict__ cow,const float* __restrict__ cob,
       const float* __restrict__ sl1g,const float* __restrict__ sl1b,
       const float* __restrict__ sl2g,const float* __restrict__ sl2b,
       const float* __restrict__ cl1g,const float* __restrict__ cl1b,
       const float* __restrict__ cl2g,const float* __restrict__ cl2b,
       const float* __restrict__ fw1,const float* __restrict__ fb1,
       const float* __restrict__ fw2,const float* __restrict__ fb2,
       const float* __restrict__ gw1,const float* __restrict__ gb1,
       const float* __restrict__ gw2,const float* __restrict__ gb2,
       const float* __restrict__ iw,const float* __restrict__ av,
       const int* __restrict__ eidx,const int* __restrict__ dst,int N,int E)
{
    extern __shared__ float sm[];
    float* s_tok = sm + O_TOK;  float* s_x = sm + O_X;
    float* s_buf = sm + O_BUF;  float* s_w = sm + O_W;
    float* s_inst= sm + O_INST; float* s_q = sm + O_Q;
    float* s_fv  = sm + O_FV;   float* s_den = sm + O_DEN;
    int* s_idx = (int*)(sm + O_INT);
    int* s_dst = s_idx + ROWS;  int* s_lid = s_dst + TILE;
    int tid = threadIdx.x, e0 = blockIdx.x * TILE;

    // S0: indices, validity, stats, gather tokens(+pos)
    if (tid < ROWS){
        int e = tid/SEQ, s = tid - e*SEQ, ge = e0 + e;
        int id = (ge < E) ? eidx[ge*SEQ + s] : N;
        s_idx[tid] = id; s_fv[tid] = (id < N) ? 1.f : 0.f;
    }
    __syncthreads();
    if (tid < TILE){
        float c = 0.f;
        for (int s=0;s<SEQ;s++) c += s_fv[tid*SEQ+s];
        s_den[tid] = fmaxf(c, 1.f);
        int lp = (c > 0.f) ? (int)c - 1 : 0;
        s_lid[tid] = s_idx[tid*SEQ + lp];
        int ge = e0 + tid;
        s_dst[tid] = (ge < E) ? dst[ge] : 0;
    }
    for (int i = tid; i < ROWS*64; i += NT){
        int r = i>>6, c = i&63, s = r%SEQ, id = s_idx[r];
        s_tok[i] = (id < N) ? __ldg(feat + (size_t)id*64 + c) + __ldg(pos + s*64 + c) : 0.f;
    }
    __syncthreads();

    // S1: LN1 + QKV (M=80, NC=192)
    ln_rows(s_tok, s_x, ROWS, sl1g, sl1b, tid);
    stage(s_w, siw, 192, 64, 68, tid);
    __syncthreads();
    gemm80(s_buf, 192, s_x, 64, s_w, 68, sib, 192, false, tid);
    __syncthreads();

    // S2: self attention, 640 items = (edge, head, q-pos), all 256 threads
    for (int it = tid; it < TILE*8*SEQ; it += NT){
        int qs = it % SEQ; int eh = it / SEQ; int h = eh & 7; int e = eh >> 3;
        const float* bb = s_buf + e*SEQ*192;
        const ull* q8 = (const ull*)(bb + qs*192 + h*8);
        ull q0=q8[0], q1=q8[1], q2=q8[2], q3=q8[3];
        float sc[SEQ], mx = -1e30f;
#pragma unroll
        for (int ks=0; ks<SEQ; ks++){
            const ull* kk = (const ull*)(bb + ks*192 + 64 + h*8);
            ull acc = 0ull;
            fma2(acc, q0, kk[0]); fma2(acc, q1, kk[1]);
            fma2(acc, q2, kk[2]); fma2(acc, q3, kk[3]);
            float s = hsum2(acc) * 0.35355339059327373f;
            if (s_fv[e*SEQ+ks] == 0.f) s = -1e9f;
            sc[ks] = s; mx = fmaxf(mx, s);
        }
        float sum = 0.f;
#pragma unroll
        for (int ks=0; ks<SEQ; ks++){ sc[ks] = expf(sc[ks]-mx); sum += sc[ks]; }
        float inv = 1.f/sum;
        ull o[4] = {0ull,0ull,0ull,0ull};
#pragma unroll
        for (int ks=0; ks<SEQ; ks++){
            ull w2 = bcast2(sc[ks]);
            const ull* vv = (const ull*)(bb + ks*192 + 128 + h*8);
            fma2(o[0], w2, vv[0]); fma2(o[1], w2, vv[1]);
            fma2(o[2], w2, vv[2]); fma2(o[3], w2, vv[3]);
        }
        float* op = s_x + (e*SEQ+qs)*64 + h*8;
#pragma unroll
        for (int j=0;j<4;j++){
            float lo, hi; unpack2(o[j], lo, hi);
            op[2*j] = lo*inv; op[2*j+1] = hi*inv;
        }
    }
    stage(s_w, sow, 64, 64, 68, tid);
    __syncthreads();
    gemm80(s_tok, 64, s_x, 64, s_w, 68, sob, 64, true, tid);
    __syncthreads();

    // S3: masked mean pool
    for (int i = tid; i < TILE*64; i += NT){
        int e = i>>6, c = i&63; float s = 0.f;
#pragma unroll
        for (int ss=0; ss<SEQ; ss++) s += s_fv[e*SEQ+ss]*s_tok[(e*SEQ+ss)*64+c];
        s_inst[i] = s / s_den[e];
    }
    __syncthreads();

    // S4: FF (sa)
    ln_rows(s_inst, s_x, TILE, sl2g, sl2b, tid);
    stage(s_w, fw1, 256, 64, 68, tid);
    __syncthreads();
    gemm16(s_buf, 256, s_x, 64, s_w, 68, fb1, 256, 64, false, tid, s_x+1024);
    __syncthreads();
    for (int i = tid; i < TILE*256; i += NT) s_buf[i] = geluf(s_buf[i]);
    stage(s_w, fw2, 64, 256, 260, tid);
    __syncthreads();
    gemm16(s_inst, 64, s_buf, 256, s_w, 260, fb2, 64, 256, true, tid, s_x);
    __syncthreads();

    // S5: cross attention
    for (int i = tid; i < TILE*64; i += NT){
        int e = i>>6, c = i&63, id = s_lid[e];
        s_x[i] = (id < N) ? __ldg(feat + (size_t)id*64 + c) : 0.f;
    }
    __syncthreads();
    ln_rows(s_x, s_x, TILE, cl1g, cl1b, tid);
    stage(s_w, ciw, 192, 64, 68, tid);
    __syncthreads();
    gemm16(s_q, 64, s_x, 64, s_w, 68, cib, 64, 64, false, tid, s_x+1024);
    __syncthreads();
    gemm80(s_buf+64, 192, s_tok, 64, s_w+64*68, 68, cib+64, 128, false, tid);
    __syncthreads();
    if (tid < TILE*8){
        int e = tid>>3, h = tid&7;
        const ull* qq = (const ull*)(s_q + e*64 + h*8);
        ull q0=qq[0], q1=qq[1], q2=qq[2], q3=qq[3];
        float sc[SEQ], mx = -1e30f;
#pragma unroll
        for (int ks=0; ks<SEQ; ks++){
            const ull* kk = (const ull*)(s_buf + (e*SEQ+ks)*192 + 64 + h*8);
            ull acc = 0ull;
            fma2(acc, q0, kk[0]); fma2(acc, q1, kk[1]);
            fma2(acc, q2, kk[2]); fma2(acc, q3, kk[3]);
            float s = hsum2(acc) * 0.35355339059327373f;
            if (s_fv[e*SEQ+ks] == 0.f) s = -1e9f;
            sc[ks] = s; mx = fmaxf(mx, s);
        }
        float sum = 0.f;
#pragma unroll
        for (int ks=0; ks<SEQ; ks++){ sc[ks] = expf(sc[ks]-mx); sum += sc[ks]; }
        float inv = 1.f/sum;
        ull o[4] = {0ull,0ull,0ull,0ull};
#pragma unroll
        for (int ks=0; ks<SEQ; ks++){
            ull w2 = bcast2(sc[ks]);
            const ull* vv = (const ull*)(s_buf + (e*SEQ+ks)*192 + 128 + h*8);
            fma2(o[0], w2, vv[0]); fma2(o[1], w2, vv[1]);
            fma2(o[2], w2, vv[2]); fma2(o[3], w2, vv[3]);
        }
        float* op = s_x + e*64 + h*8;
#pragma unroll
        for (int j=0;j<4;j++){
            float lo, hi; unpack2(o[j], lo, hi);
            op[2*j] = lo*inv; op[2*j+1] = hi*inv;
        }
    }
    stage(s_w, cow, 64, 64, 68, tid);
    __syncthreads();
    gemm16(s_inst, 64, s_x, 64, s_w, 68, cob, 64, 64, true, tid, s_x+1024);
    __syncthreads();

    // S6: FF (ca)
    ln_rows(s_inst, s_x, TILE, cl2g, cl2b, tid);
    stage(s_w, gw1, 256, 64, 68, tid);
    __syncthreads();
    gemm16(s_buf, 256, s_x, 64, s_w, 68, gb1, 256, 64, false, tid, s_x+1024);
    __syncthreads();
    for (int i = tid; i < TILE*256; i += NT) s_buf[i] = geluf(s_buf[i]);
    stage(s_w, gw2, 64, 256, 260, tid);
    __syncthreads();
    gemm16(s_inst, 64, s_buf, 256, s_w, 260, gb2, 64, 256, true, tid, s_x);
    __syncthreads();

    // S7: eft = inst @ inst_w^T (2 chunks of 256 cols) + score + seg max
    for (int ch = 0; ch < 2; ch++){
        stage(s_w, iw + ch*256*64, 256, 64, 68, tid);
        __syncthreads();
        gemm16(s_buf, 256, s_inst, 64, s_w, 68, (const float*)0, 256, 64, false, tid, s_x);
        __syncthreads();
        for (int i = tid; i < TILE*256; i += NT){
            int r = i>>8, c = i&255, ge = e0 + r;
            if (ge < E) g_eft[(size_t)ge*512 + ch*256 + c] = s_buf[i];
        }
        if (tid < TILE*4){
            int e = tid>>2, h4 = tid&3, h = ch*4+h4, ge = e0 + e;
            float v = 0.f;
            for (int d=0; d<64; d++) v += s_buf[e*256 + h4*64 + d]*__ldg(av + h*64 + d);
            v = (v > 0.f) ? v : 0.01f*v;
            if (ge < E){
                g_a[ge*8+h] = v;
                atomicMax(&g_mx[(size_t)s_dst[e]*8 + h], fkey(v));
            }
        }
        __syncthreads();
    }
}

__global__ void k_init(float* out, long long total, int n8){
    long long i = (long long)blockIdx.x*NT + threadIdx.x;
    if (i < total) out[i] = 0.f;
    if (i < n8){ g_mx[i] = 0u; g_sm[i] = 0.f; }
}

__global__ void k_exp(const int* __restrict__ dst, int E){
    int i = blockIdx.x*NT + threadIdx.x;
    if (i >= E*8) return;
    int e = i>>3, h = i&7, d = dst[e];
    float ae = expf(g_a[i] - kdec(g_mx[(size_t)d*8+h]));
    g_aexp[i] = ae;
    atomicAdd(&g_sm[(size_t)d*8+h], ae);
}

__global__ void k_scatter(const int* __restrict__ dst, float* __restrict__ out, int E){
    int t = blockIdx.x*NT + threadIdx.x;
    int e = t >> 7;
    if (e >= E) return;
    int j = (t & 127) * 4, h = j >> 6, d = dst[e];
    float w = g_aexp[e*8+h] / g_sm[(size_t)d*8+h];
    float4 v = *(const float4*)(g_eft + (size_t)e*512 + j);
    float* p = out + (size_t)d*512 + j;
    atomicAdd(p+0, v.x*w); atomicAdd(p+1, v.y*w);
    atomicAdd(p+2, v.z*w); atomicAdd(p+3, v.w*w);
}

extern "C" void kernel_launch(void* const* d_in, const int* in_sizes, int n_in,
                              void* d_out, int out_size)
{
    const float* feat=(const float*)d_in[0];  const float* pos=(const float*)d_in[1];
    const float* siw=(const float*)d_in[2];   const float* sib=(const float*)d_in[3];
    const float* sow=(const float*)d_in[4];   const float* sob=(const float*)d_in[5];
    const float* ciw=(const float*)d_in[6];   const float* cib=(const float*)d_in[7];
    const float* cow=(const float*)d_in[8];   const float* cob=(const float*)d_in[9];
    const float* sl1g=(const float*)d_in[10]; const float* sl1b=(const float*)d_in[11];
    const float* sl2g=(const float*)d_in[12]; const float* sl2b=(const float*)d_in[13];
    const float* cl1g=(const float*)d_in[14]; const float* cl1b=(const float*)d_in[15];
    const float* cl2g=(const float*)d_in[16]; const float* cl2b=(const float*)d_in[17];
    const float* fw1=(const float*)d_in[18];  const float* fb1=(const float*)d_in[19];
    const float* fw2=(const float*)d_in[20];  const float* fb2=(const float*)d_in[21];
    const float* gw1=(const float*)d_in[22];  const float* gb1=(const float*)d_in[23];
    const float* gw2=(const float*)d_in[24];  const float* gb2=(const float*)d_in[25];
    const float* iw=(const float*)d_in[26];   const float* av=(const float*)d_in[27];
    const int* eidx=(const int*)d_in[28];     const int* dst=(const int*)d_in[29];

    int N = in_sizes[0] / 64;
    int E = in_sizes[29];
    float* out = (float*)d_out;
    long long total = (long long)N * 512;

    static int attr_done = 0;
    if (!attr_done){
        cudaFuncSetAttribute(k_mega, cudaFuncAttributeMaxDynamicSharedMemorySize, SMEM_BYTES);
        attr_done = 1;
    }

    k_init<<<(unsigned)((total + NT-1)/NT), NT>>>(out, total, N*8);
    int tiles = (E + TILE - 1) / TILE;
    k_mega<<<tiles, NT, SMEM_BYTES>>>(feat,pos,siw,sib,sow,sob,ciw,cib,cow,cob,
        sl1g,sl1b,sl2g,sl2b,cl1g,cl1b,cl2g,cl2b,
        fw1,fb1,fw2,fb2,gw1,gb1,gw2,gb2,iw,av,eidx,dst,N,E);
    k_exp<<<(E*8 + NT-1)/NT, NT>>>(dst, E);
    k_scatter<<<(E*128 + NT-1)/NT, NT>>>(dst, out, E);
}